// round 17
// baseline (speedup 1.0000x reference)
#include <cuda_runtime.h>
#include <cuda_fp16.h>
#include <math.h>
#include <stdint.h>

#define N_INST 32768
#define D      2048
#define DP     512
#define CLASSES 4

#define TM 256            // instances per CTA
#define TN 128            // j per CTA
#define NSTOT 32          // 32 k-tiles of 64

// smem layout (dynamic, from 1024-aligned base sb):
//   st   (fp32 A staging) : 2 x 65536  @ 0
//   fA   (fp16 A stages)  : 2 x 32768  @ 131072
//   B    (fp16 B stages)  : 2 x 16384  @ 196608
//   Wsh                   : 512        @ 229376
// epilogue 'part' overlays st @ 0.
#define OFF_FA  131072
#define OFF_B   196608
#define OFF_W   229376
#define SMEM_BYTES (229376 + 512 + 1024)

// ---------------- scratch (module-scope, no runtime allocation) ----------------
__device__ __align__(1024) uint8_t g_Vh[(size_t)N_INST * D * 2];   // fp16 V (written by GEMM j0 CTAs, read by pool)
__device__ __align__(1024) uint8_t g_Uh[DP * D * 2];               // fp16 U
__device__ float g_Sp[4][N_INST];
__device__ float g_S[N_INST];
__device__ float g_bm[64], g_bz[64];
__device__ float g_tp[128][D];
__device__ float g_t[D];

// ---------------- PTX helpers ----------------
static __device__ __forceinline__ uint32_t smem_u32(const void* p) {
    uint32_t a;
    asm("{ .reg .u64 t; cvta.to.shared.u64 t, %1; cvt.u32.u64 %0, t; }" : "=r"(a) : "l"(p));
    return a;
}
static __device__ __forceinline__ void cp16(uint32_t dst, const void* src) {
    asm volatile("cp.async.cg.shared.global [%0], [%1], 16;" :: "r"(dst), "l"(src) : "memory");
}
static __device__ __forceinline__ void ldsm4(uint32_t* r, uint32_t addr) {
    asm volatile("ldmatrix.sync.aligned.m8n8.x4.shared.b16 {%0,%1,%2,%3}, [%4];"
                 : "=r"(r[0]), "=r"(r[1]), "=r"(r[2]), "=r"(r[3]) : "r"(addr));
}
static __device__ __forceinline__ void mma16816(float* d, const uint32_t* a, uint32_t b0, uint32_t b1) {
    asm volatile("mma.sync.aligned.m16n8k16.row.col.f32.f16.f16.f32 "
                 "{%0,%1,%2,%3}, {%4,%5,%6,%7}, {%8,%9}, {%0,%1,%2,%3};"
                 : "+f"(d[0]), "+f"(d[1]), "+f"(d[2]), "+f"(d[3])
                 : "r"(a[0]), "r"(a[1]), "r"(a[2]), "r"(a[3]), "r"(b0), "r"(b1));
}

// ---------------- packU only (2MB, trivial) ----------------
__global__ __launch_bounds__(256) void k_packU(const float* __restrict__ U) {
    const uint32_t stride = 128 * 256;
    uint32_t idx = blockIdx.x * 256 + threadIdx.x;
    #pragma unroll 4
    for (int it = 0; it < 8; ++it, idx += stride) {
        float4 v = ((const float4*)U)[idx];
        __half2 h01 = __floats2half2_rn(v.x, v.y);
        __half2 h23 = __floats2half2_rn(v.z, v.w);
        ((uint2*)g_Uh)[idx] = make_uint2(*(uint32_t*)&h01, *(uint32_t*)&h23);
    }
}

// ---------------- fused GEMM: fp32 V streamed + converted in-kernel ----------------
__global__ void k_scores_tc(const float* __restrict__ V, const float* __restrict__ Wm)
{
    extern __shared__ uint8_t dsm[];
    uint32_t raw = smem_u32(dsm);
    uint32_t sb  = (raw + 1023) & ~1023u;
    uint8_t* sp  = dsm + (sb - raw);
    float* Wsh   = (float*)(sp + OFF_W);
    float* part  = (float*)sp;                 // epilogue overlay on st

    const int tid  = threadIdx.x;
    const int lane = tid & 31, wid = tid >> 5;          // 8 warps
    const int wm = wid & 3, wn = wid >> 2;              // warp tile: rows wm*64, cols wn*64
    const int ibase = blockIdx.x * TM;
    const int jbase = blockIdx.y * TN;
    const bool wrV  = (blockIdx.y == 0);                // j0 CTAs persist fp16 V for pool

    if (tid < TN) Wsh[tid] = Wm[jbase + tid];

    const float*   aF = V + (size_t)ibase * D;
    const uint8_t* bT = g_Uh + (size_t)jbase * (D * 2);

    // B loader constants (16B chunks, 4 per thread)
    const uint32_t lrow   = tid >> 3;                   // 0..31
    const uint32_t lc16   = (tid & 7) * 16;
    const uint32_t ld_dst = lc16 ^ ((lrow & 7) << 4);

    // ldmatrix constants (unchanged hot path)
    const uint32_t mask  = (lane & 7) << 4;
    const uint32_t aRow  = (wm * 64 + (lane & 15)) * 128;
    const uint32_t bRow  = (wn * 64 + (lane & 7) + ((lane >> 1) & 8)) * 128;
    const uint32_t kselA = (lane & 16);
    const uint32_t kselB = (lane & 8) << 1;

    float acc[4][8][4];
    #pragma unroll
    for (int a = 0; a < 4; ++a)
        #pragma unroll
        for (int b = 0; b < 8; ++b)
            #pragma unroll
            for (int c = 0; c < 4; ++c) acc[a][b][c] = 0.f;

    // issue group s: fp32 A(s) -> st[s&1], fp16 B(s) -> Bbuf[s&1]
    auto issue = [&](int s) {
        const uint32_t stq = sb + (s & 1) * 65536;
        const float*   as  = aF + s * 64;
        #pragma unroll
        for (int q = 0; q < 16; ++q) {
            uint32_t c = q * 256 + tid;
            uint32_t row = c >> 4, col = c & 15;        // 256 rows x 16 chunks(16B)
            cp16(stq + row * 256 + col * 16, as + (size_t)row * D + col * 4);
        }
        const uint8_t* bs = bT + (size_t)s * 128;
        const uint32_t dB = sb + OFF_B + (s & 1) * 16384;
        #pragma unroll
        for (int q = 0; q < 4; ++q) {
            uint32_t row = lrow + q * 32;
            cp16(dB + row * 128 + ld_dst, bs + (size_t)row * 4096 + lc16);
        }
        asm volatile("cp.async.commit_group;" ::: "memory");
    };

    // convert stage ss: st[ss&1] (fp32) -> fA[ss&1] (fp16, swizzled); j0 also -> g_Vh
    auto convert = [&](int ss) {
        const uint32_t stq = sb + (ss & 1) * 65536;
        const uint32_t fAq = sb + OFF_FA + (ss & 1) * 32768;
        #pragma unroll
        for (int q = 0; q < 16; ++q) {
            uint32_t c = q * 256 + tid;
            uint32_t row = c >> 4, col = c & 15;
            float4 v;
            asm volatile("ld.shared.v4.f32 {%0,%1,%2,%3}, [%4];"
                         : "=f"(v.x), "=f"(v.y), "=f"(v.z), "=f"(v.w)
                         : "r"(stq + row * 256 + col * 16));
            __half2 h01 = __floats2half2_rn(v.x, v.y);
            __half2 h23 = __floats2half2_rn(v.z, v.w);
            uint32_t u0 = *(uint32_t*)&h01, u1 = *(uint32_t*)&h23;
            uint32_t dst = fAq + row * 128 + ((col * 8) ^ ((row & 7) << 4));
            asm volatile("st.shared.v2.u32 [%0], {%1,%2};" :: "r"(dst), "r"(u0), "r"(u1));
            if (wrV)
                *(uint2*)(g_Vh + ((size_t)(ibase + row) * D + ss * 64 + col * 4) * 2)
                    = make_uint2(u0, u1);
        }
    };

    issue(0); issue(1);
    asm volatile("cp.async.wait_group 1;" ::: "memory");   // g0 done
    __syncthreads();
    convert(0);

    #pragma unroll 1
    for (int s = 0; s < NSTOT; ++s) {
        asm volatile("cp.async.wait_group 0;" ::: "memory");  // g(s+1) done
        __syncthreads();                                      // fA(s) visible; st[s&1] free
        if (s + 1 < NSTOT) convert(s + 1);                    // overlaps MMA(s)

        const uint32_t smA = sb + OFF_FA + (s & 1) * 32768;
        const uint32_t smB = sb + OFF_B  + (s & 1) * 16384;
        #pragma unroll
        for (int kk = 0; kk < 4; ++kk) {
            const uint32_t kxA = (kk * 32 + kselA) ^ mask;
            const uint32_t kxB = (kk * 32 + kselB) ^ mask;
            uint32_t Af[4][4], Bf[4][4];
            #pragma unroll
            for (int mt = 0; mt < 4; ++mt) ldsm4(Af[mt], smA + aRow + mt * 2048 + kxA);
            #pragma unroll
            for (int p = 0; p < 4; ++p)   ldsm4(Bf[p],  smB + bRow + p  * 2048 + kxB);
            #pragma unroll
            for (int mt = 0; mt < 4; ++mt)
                #pragma unroll
                for (int nt = 0; nt < 8; ++nt) {
                    const uint32_t* B = Bf[nt >> 1];
                    mma16816(acc[mt][nt], Af[mt],
                             (nt & 1) ? B[2] : B[0], (nt & 1) ? B[3] : B[1]);
                }
        }
        __syncthreads();                                      // MMA/convert done before reuse
        if (s + 2 < NSTOT) issue(s + 2);
    }

    // ---- epilogue: s_part[i] = sum_{j in tile} w_j * tanh(c_ij) ----
    const int gr = lane >> 2;
    const int gc = (lane & 3) * 2;
    #pragma unroll
    for (int mt = 0; mt < 4; ++mt) {
        float l0 = 0.f, l1 = 0.f;
        #pragma unroll
        for (int nt = 0; nt < 8; ++nt) {
            int wi = wn * 64 + nt * 8 + gc;
            float w0 = Wsh[wi], w1 = Wsh[wi + 1];
            l0 += w0 * tanhf(acc[mt][nt][0]) + w1 * tanhf(acc[mt][nt][1]);
            l1 += w0 * tanhf(acc[mt][nt][2]) + w1 * tanhf(acc[mt][nt][3]);
        }
        l0 += __shfl_xor_sync(0xffffffffu, l0, 1);
        l0 += __shfl_xor_sync(0xffffffffu, l0, 2);
        l1 += __shfl_xor_sync(0xffffffffu, l1, 1);
        l1 += __shfl_xor_sync(0xffffffffu, l1, 2);
        if ((lane & 3) == 0) {
            part[wn * 256 + wm * 64 + mt * 16 + gr]     = l0;
            part[wn * 256 + wm * 64 + mt * 16 + 8 + gr] = l1;
        }
    }
    __syncthreads();
    if (tid < 256) {
        float sv = part[tid] + part[256 + tid];
        g_Sp[blockIdx.y][ibase + tid] = sv;
    }
}

// ---------------- softmax stage 1: per-512-block max & partial Z ----------------
__global__ __launch_bounds__(512) void k_smax1() {
    __shared__ float sm[512];
    const int tid = threadIdx.x;
    const int i = blockIdx.x * 512 + tid;
    float s = g_Sp[0][i] + g_Sp[1][i] + g_Sp[2][i] + g_Sp[3][i];
    g_S[i] = s;
    sm[tid] = s; __syncthreads();
    for (int o = 256; o > 0; o >>= 1) {
        if (tid < o) sm[tid] = fmaxf(sm[tid], sm[tid + o]);
        __syncthreads();
    }
    const float bm = sm[0];
    __syncthreads();
    sm[tid] = expf(s - bm); __syncthreads();
    for (int o = 256; o > 0; o >>= 1) {
        if (tid < o) sm[tid] += sm[tid + o];
        __syncthreads();
    }
    if (tid == 0) { g_bm[blockIdx.x] = bm; g_bz[blockIdx.x] = sm[0]; }
}

// ---------------- pooling: fp16 V, fused softmax finalize + normalize ----------------
__global__ __launch_bounds__(256) void k_pool() {
    __shared__ float ash[256];
    __shared__ float sMZ[2];
    const int tid = threadIdx.x;
    const int c   = blockIdx.x * 1024 + tid * 4;
    const int i0  = blockIdx.y * 256;

    if (tid < 32) {
        float m = fmaxf(g_bm[tid], g_bm[tid + 32]);
        #pragma unroll
        for (int o = 16; o > 0; o >>= 1) m = fmaxf(m, __shfl_xor_sync(0xffffffffu, m, o));
        if (tid == 0) sMZ[0] = m;
    }
    __syncthreads();
    if (tid < 32) {
        float M = sMZ[0];
        float z = g_bz[tid] * expf(g_bm[tid] - M) + g_bz[tid + 32] * expf(g_bm[tid + 32] - M);
        #pragma unroll
        for (int o = 16; o > 0; o >>= 1) z += __shfl_xor_sync(0xffffffffu, z, o);
        if (tid == 0) sMZ[1] = 1.0f / z;
    }
    __syncthreads();
    const float M = sMZ[0], invZ = sMZ[1];

    ash[tid] = expf(g_S[i0 + tid] - M) * invZ;
    __syncthreads();

    float4 acc = make_float4(0.f, 0.f, 0.f, 0.f);
    const uint2* vp = (const uint2*)(g_Vh + ((size_t)i0 * D + c) * 2);
    #pragma unroll 8
    for (int i = 0; i < 256; ++i) {
        float a = ash[i];
        uint2 r = vp[(size_t)i * (D / 4)];
        float2 f0 = __half22float2(*(const __half2*)&r.x);
        float2 f1 = __half22float2(*(const __half2*)&r.y);
        acc.x += a * f0.x; acc.y += a * f0.y;
        acc.z += a * f1.x; acc.w += a * f1.y;
    }
    *(float4*)&g_tp[blockIdx.y][c] = acc;
}
__global__ void k_pool_reduce() {
    const int k = blockIdx.x * blockDim.x + threadIdx.x;
    float s = 0.f;
    #pragma unroll
    for (int r = 0; r < 128; ++r) s += g_tp[r][k];
    g_t[k] = s;
}

// ---------------- final linear ----------------
__global__ void k_final(const float* __restrict__ W, float* __restrict__ out) {
    const int c    = threadIdx.y;
    const int lane = threadIdx.x;
    float s = 0.f;
    for (int k = lane; k < D; k += 32) s += W[c * D + k] * g_t[k];
    #pragma unroll
    for (int o = 16; o > 0; o >>= 1) s += __shfl_down_sync(0xffffffff, s, o);
    if (lane == 0) out[c] = s;
}

// ---------------- launcher (single stream; packV eliminated) ----------------
extern "C" void kernel_launch(void* const* d_in, const int* in_sizes, int n_in,
                              void* d_out, int out_size)
{
    const float* V  = (const float*)d_in[0];   // V_prime [32768, 2048]
    const float* U  = (const float*)d_in[1];   // U_t     [512, 2048]
    const float* Wm = (const float*)d_in[2];   // W_mta   [1, 512]
    const float* W  = (const float*)d_in[3];   // W       [4, 2048]
    float* out = (float*)d_out;

    cudaFuncSetAttribute(k_scores_tc, cudaFuncAttributeMaxDynamicSharedMemorySize, SMEM_BYTES);

    k_packU<<<128, 256>>>(U);
    k_scores_tc<<<dim3(128, 4), 256, SMEM_BYTES>>>(V, Wm);
    k_smax1<<<64, 512>>>();
    k_pool<<<dim3(2, 128), 256>>>();
    k_pool_reduce<<<2, 1024>>>();
    k_final<<<1, dim3(32, 4)>>>(W, out);
}